// round 16
// baseline (speedup 1.0000x reference)
#include <cuda_runtime.h>
#include <cuda_fp16.h>

#define BATCH 8
#define SEQ   1024
#define EMB   512
#define HEADS 8
#define DK    64
#define NP    4            // wire pairs
#define BH    (BATCH*HEADS)
#define TM    128          // rows per CTA (4 warps x m=32)
#define TJ    128          // j-tile
#define NT    (SEQ/TJ)     // 8 tiles
#define VSTR2 72           // V smem row stride in u32: (8tig+g+8nb)%32 conflict-free

// sqrt(log2(e)): pair-0 u carries this on both sides -> score scaled by log2(e).
#define SQRT_LOG2E 1.2011224087864498f
#define ONES_H2   0x3C003C00u   // fp16x2 {1.0, 1.0}

// Precomputed tables (device globals; allocation is forbidden)
__device__ uint4 g_uq[BH*NP*SEQ];        // i-side {h01,h23,l01,l23}
__device__ uint2 g_ub[BH*NP*SEQ*2];      // j-side {h,l} per comp-half
__device__ unsigned g_vp[(size_t)BH*(SEQ/2)*DK];  // fp16x2 {V[2jp+1], V[2jp]}

static __device__ __forceinline__ unsigned pkf16(float hi, float lo){
    unsigned r; asm("cvt.rn.f16x2.f32 %0, %1, %2;" : "=r"(r) : "f"(hi), "f"(lo)); return r;
}
static __device__ __forceinline__ unsigned ex2h2(unsigned x){
    unsigned r; asm("ex2.approx.f16x2 %0, %1;" : "=r"(r) : "r"(x)); return r;
}

// m16n8k16 f16 MMA, f32 accum, zero C
#define MMA_F16_Z(D, A0, A1, A2, A3, B0, B1)                                \
    asm volatile("mma.sync.aligned.m16n8k16.row.col.f32.f16.f16.f32 "       \
        "{%0,%1,%2,%3}, {%4,%5,%6,%7}, {%8,%9}, {%10,%10,%10,%10};"         \
        : "=f"((D)[0]), "=f"((D)[1]), "=f"((D)[2]), "=f"((D)[3])            \
        : "r"(A0), "r"(A1), "r"(A2), "r"(A3), "r"(B0), "r"(B1), "f"(0.f))
// m16n8k16 f16 MMA, f32 accum, D += A*B
#define MMA_F16_ACC(D, A0, A1, A2, A3, B0, B1)                              \
    asm volatile("mma.sync.aligned.m16n8k16.row.col.f32.f16.f16.f32 "       \
        "{%0,%1,%2,%3}, {%4,%5,%6,%7}, {%8,%9}, {%0,%1,%2,%3};"             \
        : "+f"((D)[0]), "+f"((D)[1]), "+f"((D)[2]), "+f"((D)[3])            \
        : "r"(A0), "r"(A1), "r"(A2), "r"(A3), "r"(B0), "r"(B1))

// Pass 1 (fused): blocks [0,1024) build u tables; blocks [1024,9216) build V.
__global__ void precompute_all(const float* __restrict__ x){
    if (blockIdx.x < 1024){
        int idx = blockIdx.x*blockDim.x + threadIdx.x;   // (bh*NP + p)*SEQ + s
        int s   = idx & (SEQ-1);
        int bhp = idx >> 10;
        int p   = bhp & (NP-1);
        int bh  = bhp >> 2;
        int b = bh >> 3, h = bh & 7;
        float2 xv = *(const float2*)&x[((size_t)(b*SEQ+s))*EMB + h*DK + 2*p];
        float sa, ca, sb, cb;
        sincosf(0.5f*xv.x, &sa, &ca);
        sincosf(0.5f*xv.y, &sb, &cb);
        float sc = (p == 0) ? SQRT_LOG2E : 1.0f;
        float u0 = sc*ca*cb, u1 = sc*ca*sb, u2 = sc*sa*cb, u3 = sc*sa*sb;
        float h0 = __half2float(__float2half_rn(u0));
        float h1 = __half2float(__float2half_rn(u1));
        float h2 = __half2float(__float2half_rn(u2));
        float h3 = __half2float(__float2half_rn(u3));
        unsigned h01 = pkf16(u1, u0), h23 = pkf16(u3, u2);
        unsigned l01 = pkf16(u1 - h1, u0 - h0), l23 = pkf16(u3 - h3, u2 - h2);
        g_uq[idx] = make_uint4(h01, h23, l01, l23);
        g_ub[idx*2 + 0] = make_uint2(h01, l01);
        g_ub[idx*2 + 1] = make_uint2(h23, l23);
    } else {
        int idx = (blockIdx.x - 1024)*blockDim.x + threadIdx.x; // (bh*512+jp)*64+col
        int col = idx & 63;
        int jp  = (idx >> 6) & 511;
        int bh  = idx >> 15;
        int b = bh >> 3, h = bh & 7;
        float v0 = x[((size_t)(b*SEQ + 2*jp    ))*EMB + h*DK + col];
        float v1 = x[((size_t)(b*SEQ + 2*jp + 1))*EMB + h*DK + col];
        g_vp[idx] = pkf16(v1, v0);
    }
}

// Pass 2: QK (fp16-split k16 MMA) -> f16x2 ex2 -> PV + ones-column sum MMA
// -> normalize. 4 warps; warp w owns rows [w*32,w*32+32) as 2 m16 blocks.
// TJ=128: 8 tiles, half the syncs/staging overhead of TJ=64.
__global__ void __launch_bounds__(128, 4)
qk_attn12(float* __restrict__ out){
    __shared__ __align__(16) uint2    sUB[NP][TJ][2];   // j-side {h,l} per comp-half (8 KB)
    __shared__ __align__(16) unsigned sV[(TJ/2)*VSTR2]; // fp16x2 j-pairs (18 KB)

    const int bh = blockIdx.y, b = bh >> 3, h = bh & 7;
    const int tid = threadIdx.x;
    const int w   = tid >> 5;
    const int lane = tid & 31;
    const int g   = lane >> 2, tig = lane & 3;
    const int rowbase = blockIdx.x*TM + w*32;
    const bool lo2 = (tig < 2);
    const int chalf = tig & 1;

    // i-side A-frag bases
    unsigned ai0[2][NP], ai1[2][NP];
    {
        const unsigned* gu = (const unsigned*)g_uq;
#pragma unroll
        for (int blk = 0; blk < 2; ++blk)
#pragma unroll
            for (int p = 0; p < NP; ++p){
                int row = rowbase + blk*16 + g;
                size_t base = ((size_t)(bh*NP + p)*SEQ + row)*4 + tig;
                ai0[blk][p] = gu[base];
                ai1[blk][p] = gu[base + 32];
            }
    }

    float acc[2][8][4];
    float acc2[2][4];   // ones-column row sums: [blk]{row g: c0, row g+8: c2}
#pragma unroll
    for (int blk = 0; blk < 2; ++blk){
#pragma unroll
        for (int nb = 0; nb < 8; ++nb)
#pragma unroll
            for (int k = 0; k < 4; ++k) acc[blk][nb][k] = 0.f;
#pragma unroll
        for (int k = 0; k < 4; ++k) acc2[blk][k] = 0.f;
    }

    for (int jt = 0; jt < NT; ++jt){
        const int j0 = jt*TJ;
        // stage j-side u: NP*TJ = 512 entries of 16 B -> 4 uint4 per thread
#pragma unroll
        for (int r = 0; r < 4; ++r){
            int e = tid + r*128;
            int p = e >> 7, jj = e & 127;
            *(uint4*)&sUB[p][jj][0] =
                ((const uint4*)g_ub)[(size_t)(bh*NP + p)*SEQ + j0 + jj];
        }
        // stage V tile: 64 jp x 16 uint4 = 1024 uint4 -> 8 per thread
#pragma unroll
        for (int r = 0; r < 8; ++r){
            int l = tid + r*128;
            int row = l >> 4, c4 = l & 15;
            *(uint4*)&sV[row*VSTR2 + c4*4] =
                ((const uint4*)g_vp)[((size_t)bh*512 + (j0 >> 1) + row)*16 + c4];
        }
        __syncthreads();

#pragma unroll
        for (int m = 0; m < TJ/16; ++m){        // kb-pairs: j = 16m .. 16m+15
            unsigned pa[2][4];                  // PV A-frags per blk
#pragma unroll
            for (int half = 0; half < 2; ++half){
                const int kb = 2*m + half;
                float q0[4], q1[4];
#pragma unroll
                for (int p = 0; p < NP; ++p){
                    uint2 ub = sUB[p][kb*8 + g][chalf];
                    unsigned b0 = ub.x;
                    unsigned b1 = lo2 ? ub.y : 0u;
                    {
                        unsigned a0 = ai0[0][p], a1 = ai1[0][p];
                        unsigned a2 = lo2 ? a0 : 0u, a3 = lo2 ? a1 : 0u;
                        float d[4];
                        MMA_F16_Z(d, a0, a1, a2, a3, b0, b1);
                        if (p == 0){ q0[0]=d[0]; q0[1]=d[1]; q0[2]=d[2]; q0[3]=d[3]; }
                        else       { q0[0]*=d[0]; q0[1]*=d[1]; q0[2]*=d[2]; q0[3]*=d[3]; }
                    }
                    {
                        unsigned a0 = ai0[1][p], a1 = ai1[1][p];
                        unsigned a2 = lo2 ? a0 : 0u, a3 = lo2 ? a1 : 0u;
                        float d[4];
                        MMA_F16_Z(d, a0, a1, a2, a3, b0, b1);
                        if (p == 0){ q1[0]=d[0]; q1[1]=d[1]; q1[2]=d[2]; q1[3]=d[3]; }
                        else       { q1[0]*=d[0]; q1[1]*=d[1]; q1[2]*=d[2]; q1[3]*=d[3]; }
                    }
                }
                // q carries log2e; |.| via sign-mask; 2 exps per MUFU op.
                pa[0][half*2 + 0] = ex2h2(pkf16(q0[1], q0[0]) & 0x7FFF7FFFu);
                pa[0][half*2 + 1] = ex2h2(pkf16(q0[3], q0[2]) & 0x7FFF7FFFu);
                pa[1][half*2 + 0] = ex2h2(pkf16(q1[1], q1[0]) & 0x7FFF7FFFu);
                pa[1][half*2 + 1] = ex2h2(pkf16(q1[3], q1[2]) & 0x7FFF7FFFu);
            }
            // PV over 16 j + ones-column row-sum MMA (B = 1.0 constant)
            const unsigned* vrow0 = &sV[(m*8 + tig)*VSTR2 + g];
            const unsigned* vrow1 = &sV[(m*8 + 4 + tig)*VSTR2 + g];
#pragma unroll
            for (int nb = 0; nb < 8; ++nb){
                unsigned b0 = vrow0[8*nb];
                unsigned b1 = vrow1[8*nb];
                MMA_F16_ACC(acc[0][nb], pa[0][0], pa[0][1], pa[0][2], pa[0][3], b0, b1);
                MMA_F16_ACC(acc[1][nb], pa[1][0], pa[1][1], pa[1][2], pa[1][3], b0, b1);
            }
            MMA_F16_ACC(acc2[0], pa[0][0], pa[0][1], pa[0][2], pa[0][3], ONES_H2, ONES_H2);
            MMA_F16_ACC(acc2[1], pa[1][0], pa[1][1], pa[1][2], pa[1][3], ONES_H2, ONES_H2);
        }
        __syncthreads();
    }

    // Row sums came out of the ones-column MMA (cross-lane, full j range).
    const float inv0 = 1.0f/acc2[0][0], inv1 = 1.0f/acc2[0][2];
    const float inv2 = 1.0f/acc2[1][0], inv3 = 1.0f/acc2[1][2];

#pragma unroll
    for (int nb = 0; nb < 8; ++nb){
        size_t col = h*DK + nb*8 + 2*tig;
        size_t o0 = ((size_t)(b*SEQ + rowbase + g +  0))*EMB + col;
        size_t o1 = ((size_t)(b*SEQ + rowbase + g +  8))*EMB + col;
        size_t o2 = ((size_t)(b*SEQ + rowbase + g + 16))*EMB + col;
        size_t o3 = ((size_t)(b*SEQ + rowbase + g + 24))*EMB + col;
        *(float2*)&out[o0] = make_float2(acc[0][nb][0]*inv0, acc[0][nb][1]*inv0);
        *(float2*)&out[o1] = make_float2(acc[0][nb][2]*inv1, acc[0][nb][3]*inv1);
        *(float2*)&out[o2] = make_float2(acc[1][nb][0]*inv2, acc[1][nb][1]*inv2);
        *(float2*)&out[o3] = make_float2(acc[1][nb][2]*inv3, acc[1][nb][3]*inv3);
    }
}

extern "C" void kernel_launch(void* const* d_in, const int* in_sizes, int n_in,
                              void* d_out, int out_size){
    const float* x = (const float*)d_in[0];
    float* out = (float*)d_out;
    precompute_all<<<1024 + (BH*(SEQ/2)*DK)/256, 256>>>(x);
    dim3 grid(SEQ/TM, BH);
    qk_attn12<<<grid, 128>>>(out);
}

// round 17
// speedup vs baseline: 2.0514x; 2.0514x over previous
#include <cuda_runtime.h>
#include <cuda_fp16.h>

#define BATCH 8
#define SEQ   1024
#define EMB   512
#define HEADS 8
#define DK    64
#define BH    (BATCH*HEADS)
#define TM    128          // rows per CTA (4 warps x m=32)
#define TJ    64           // j-tile
#define NT    (SEQ/TJ)
#define VSTR2 72           // V smem row stride in u32: (8tig+g+8nb)%32 conflict-free

// sqrt(log2(e)): group-0 w carries this on both sides -> score scaled by log2(e).
#define SQRT_LOG2E 1.2011224087864498f
#define ONES_H2   0x3C003C00u   // fp16x2 {1.0, 1.0}

// Precomputed tables (device globals; allocation is forbidden)
// g_w[((bh*2+grp)*SEQ+s)*2 + q] : 16 fp16 w-vector (u_pair0 (x) u_pair1),
// chunk-permuted so uint2[t] = (chunk t, chunk t+4), t=0..3.
__device__ uint4 g_w[BH*2*SEQ*2];
__device__ unsigned g_vp[(size_t)BH*(SEQ/2)*DK];  // fp16x2 {V[2jp+1], V[2jp]}

static __device__ __forceinline__ unsigned pkf16(float hi, float lo){
    unsigned r; asm("cvt.rn.f16x2.f32 %0, %1, %2;" : "=r"(r) : "f"(hi), "f"(lo)); return r;
}
static __device__ __forceinline__ unsigned ex2h2(unsigned x){
    unsigned r; asm("ex2.approx.f16x2 %0, %1;" : "=r"(r) : "r"(x)); return r;
}

// m16n8k16 f16 MMA, f32 accum, zero C
#define MMA_F16_Z(D, A0, A1, A2, A3, B0, B1)                                \
    asm volatile("mma.sync.aligned.m16n8k16.row.col.f32.f16.f16.f32 "       \
        "{%0,%1,%2,%3}, {%4,%5,%6,%7}, {%8,%9}, {%10,%10,%10,%10};"         \
        : "=f"((D)[0]), "=f"((D)[1]), "=f"((D)[2]), "=f"((D)[3])            \
        : "r"(A0), "r"(A1), "r"(A2), "r"(A3), "r"(B0), "r"(B1), "f"(0.f))
// m16n8k16 f16 MMA, f32 accum, D += A*B
#define MMA_F16_ACC(D, A0, A1, A2, A3, B0, B1)                              \
    asm volatile("mma.sync.aligned.m16n8k16.row.col.f32.f16.f16.f32 "       \
        "{%0,%1,%2,%3}, {%4,%5,%6,%7}, {%8,%9}, {%0,%1,%2,%3};"             \
        : "+f"((D)[0]), "+f"((D)[1]), "+f"((D)[2]), "+f"((D)[3])            \
        : "r"(A0), "r"(A1), "r"(A2), "r"(A3), "r"(B0), "r"(B1))

// Pass 1 (fused): blocks [0,512) build w tables; blocks [512,8704) pack V.
__global__ void precompute_all(const float* __restrict__ x){
    if (blockIdx.x < 512){
        int idx = blockIdx.x*blockDim.x + threadIdx.x;   // (bh*2+grp)*SEQ + s
        int s   = idx & (SEQ-1);
        int gb  = idx >> 10;
        int grp = gb & 1;
        int bh  = gb >> 1;
        int b = bh >> 3, h = bh & 7;
        float4 xv = *(const float4*)&x[((size_t)(b*SEQ+s))*EMB + h*DK + 4*grp];
        float s0,c0,s1,c1,s2,c2,s3,c3;
        sincosf(0.5f*xv.x, &s0, &c0);
        sincosf(0.5f*xv.y, &s1, &c1);
        sincosf(0.5f*xv.z, &s2, &c2);
        sincosf(0.5f*xv.w, &s3, &c3);
        float sc = (grp == 0) ? SQRT_LOG2E : 1.0f;
        float ua[4] = {sc*c0*c1, sc*c0*s1, sc*s0*c1, sc*s0*s1};
        float ubv[4] = {c2*c3, c2*s3, s2*c3, s2*s3};
        unsigned ch[8];
#pragma unroll
        for (int c = 0; c < 8; ++c){
            // w[4a+bb] = ua[a]*ubv[bb]; chunk c = (w[2c], w[2c+1])
            int a0 = (2*c) >> 2,   b0 = (2*c) & 3;
            int a1 = (2*c+1) >> 2, b1 = (2*c+1) & 3;
            ch[c] = pkf16(ua[a1]*ubv[b1], ua[a0]*ubv[b0]);
        }
        // permuted: uint2[t] = (chunk t, chunk t+4)
        g_w[(size_t)idx*2 + 0] = make_uint4(ch[0], ch[4], ch[1], ch[5]);
        g_w[(size_t)idx*2 + 1] = make_uint4(ch[2], ch[6], ch[3], ch[7]);
    } else {
        int idx = (blockIdx.x - 512)*blockDim.x + threadIdx.x; // (bh*512+jp)*64+col
        int col = idx & 63;
        int jp  = (idx >> 6) & 511;
        int bh  = idx >> 15;
        int b = bh >> 3, h = bh & 7;
        float v0 = x[((size_t)(b*SEQ + 2*jp    ))*EMB + h*DK + col];
        float v1 = x[((size_t)(b*SEQ + 2*jp + 1))*EMB + h*DK + col];
        g_vp[idx] = pkf16(v1, v0);
    }
}

// Pass 2: QK via 2 merged 16-dim fp16 MMAs -> product -> f16x2 ex2 ->
// PV + ones-column sum MMA -> normalize.
// 4 warps; warp w owns rows [w*32,w*32+32) as 2 m16 blocks.
__global__ void __launch_bounds__(128, 4)
qk_attn13(float* __restrict__ out){
    __shared__ __align__(16) uint4    sW[2][TJ][2];     // j-side w (4 KB)
    __shared__ __align__(16) unsigned sV[(TJ/2)*VSTR2]; // fp16x2 j-pairs (9 KB)

    const int bh = blockIdx.y, b = bh >> 3, h = bh & 7;
    const int tid = threadIdx.x;
    const int w   = tid >> 5;
    const int lane = tid & 31;
    const int g   = lane >> 2, tig = lane & 3;
    const int rowbase = blockIdx.x*TM + w*32;

    // i-side A-frags: awr = (a0,a2) for row, aw8 = (a1,a3) for row+8
    uint2 awr[2][2], aw8[2][2];   // [blk][grp]
    {
        const uint2* gw = (const uint2*)g_w;
#pragma unroll
        for (int blk = 0; blk < 2; ++blk)
#pragma unroll
            for (int grp = 0; grp < 2; ++grp){
                int row = rowbase + blk*16 + g;
                size_t base = ((size_t)(bh*2 + grp)*SEQ + row)*4 + tig;
                awr[blk][grp] = gw[base];
                aw8[blk][grp] = gw[base + 32];   // row+8 -> +8*4 uint2
            }
    }

    float acc[2][8][4];
    float acc2[2][4];   // ones-column row sums: [blk]{row g: c0, row g+8: c2}
#pragma unroll
    for (int blk = 0; blk < 2; ++blk){
#pragma unroll
        for (int nb = 0; nb < 8; ++nb)
#pragma unroll
            for (int k = 0; k < 4; ++k) acc[blk][nb][k] = 0.f;
#pragma unroll
        for (int k = 0; k < 4; ++k) acc2[blk][k] = 0.f;
    }

    for (int jt = 0; jt < NT; ++jt){
        const int j0 = jt*TJ;
        // stage j-side w: 2 grp x 64 jj x 2 uint4 = 256 uint4 -> 2 per thread
#pragma unroll
        for (int r = 0; r < 2; ++r){
            int e = tid + r*128;
            int grp = e >> 7, rem = e & 127;
            int jj = rem >> 1, q = rem & 1;
            sW[grp][jj][q] = g_w[((size_t)(bh*2 + grp)*SEQ + j0 + jj)*2 + q];
        }
        // stage V tile: 32 jp x 16 uint4 = 512 uint4 -> 4 per thread
#pragma unroll
        for (int r = 0; r < 4; ++r){
            int l = tid + r*128;
            int row = l >> 4, c4 = l & 15;
            *(uint4*)&sV[row*VSTR2 + c4*4] =
                ((const uint4*)g_vp)[((size_t)bh*512 + (j0 >> 1) + row)*16 + c4];
        }
        __syncthreads();

#pragma unroll
        for (int m = 0; m < TJ/16; ++m){        // kb-pairs: j = 16m .. 16m+15
            unsigned pa[2][4];                  // PV A-frags per blk
#pragma unroll
            for (int half = 0; half < 2; ++half){
                const int kb = 2*m + half;
                // j-side B-frags: one LDS.64 per group, conflict-free
                uint2 ub0 = ((const uint2*)sW[0][kb*8 + g])[tig];
                uint2 ub1 = ((const uint2*)sW[1][kb*8 + g])[tig];
                float d0[4], d1[4], q0[4], q1[4];
                // blk 0: two 16-dim dots, then elementwise product
                MMA_F16_Z(d0, awr[0][0].x, aw8[0][0].x, awr[0][0].y, aw8[0][0].y,
                          ub0.x, ub0.y);
                MMA_F16_Z(d1, awr[0][1].x, aw8[0][1].x, awr[0][1].y, aw8[0][1].y,
                          ub1.x, ub1.y);
                q0[0] = d0[0]*d1[0]; q0[1] = d0[1]*d1[1];
                q0[2] = d0[2]*d1[2]; q0[3] = d0[3]*d1[3];
                // blk 1
                MMA_F16_Z(d0, awr[1][0].x, aw8[1][0].x, awr[1][0].y, aw8[1][0].y,
                          ub0.x, ub0.y);
                MMA_F16_Z(d1, awr[1][1].x, aw8[1][1].x, awr[1][1].y, aw8[1][1].y,
                          ub1.x, ub1.y);
                q1[0] = d0[0]*d1[0]; q1[1] = d0[1]*d1[1];
                q1[2] = d0[2]*d1[2]; q1[3] = d0[3]*d1[3];
                // q carries log2e; |.| via sign-mask; 2 exps per MUFU op.
                pa[0][half*2 + 0] = ex2h2(pkf16(q0[1], q0[0]) & 0x7FFF7FFFu);
                pa[0][half*2 + 1] = ex2h2(pkf16(q0[3], q0[2]) & 0x7FFF7FFFu);
                pa[1][half*2 + 0] = ex2h2(pkf16(q1[1], q1[0]) & 0x7FFF7FFFu);
                pa[1][half*2 + 1] = ex2h2(pkf16(q1[3], q1[2]) & 0x7FFF7FFFu);
            }
            // PV over 16 j + ones-column row-sum MMA (B = 1.0 constant)
            const unsigned* vrow0 = &sV[(m*8 + tig)*VSTR2 + g];
            const unsigned* vrow1 = &sV[(m*8 + 4 + tig)*VSTR2 + g];
#pragma unroll
            for (int nb = 0; nb < 8; ++nb){
                unsigned b0 = vrow0[8*nb];
                unsigned b1 = vrow1[8*nb];
                MMA_F16_ACC(acc[0][nb], pa[0][0], pa[0][1], pa[0][2], pa[0][3], b0, b1);
                MMA_F16_ACC(acc[1][nb], pa[1][0], pa[1][1], pa[1][2], pa[1][3], b0, b1);
            }
            MMA_F16_ACC(acc2[0], pa[0][0], pa[0][1], pa[0][2], pa[0][3], ONES_H2, ONES_H2);
            MMA_F16_ACC(acc2[1], pa[1][0], pa[1][1], pa[1][2], pa[1][3], ONES_H2, ONES_H2);
        }
        __syncthreads();
    }

    // Row sums came out of the ones-column MMA (cross-lane, full j range).
    const float inv0 = 1.0f/acc2[0][0], inv1 = 1.0f/acc2[0][2];
    const float inv2 = 1.0f/acc2[1][0], inv3 = 1.0f/acc2[1][2];

#pragma unroll
    for (int nb = 0; nb < 8; ++nb){
        size_t col = h*DK + nb*8 + 2*tig;
        size_t o0 = ((size_t)(b*SEQ + rowbase + g +  0))*EMB + col;
        size_t o1 = ((size_t)(b*SEQ + rowbase + g +  8))*EMB + col;
        size_t o2 = ((size_t)(b*SEQ + rowbase + g + 16))*EMB + col;
        size_t o3 = ((size_t)(b*SEQ + rowbase + g + 24))*EMB + col;
        *(float2*)&out[o0] = make_float2(acc[0][nb][0]*inv0, acc[0][nb][1]*inv0);
        *(float2*)&out[o1] = make_float2(acc[0][nb][2]*inv1, acc[0][nb][3]*inv1);
        *(float2*)&out[o2] = make_float2(acc[1][nb][0]*inv2, acc[1][nb][1]*inv2);
        *(float2*)&out[o3] = make_float2(acc[1][nb][2]*inv3, acc[1][nb][3]*inv3);
    }
}

extern "C" void kernel_launch(void* const* d_in, const int* in_sizes, int n_in,
                              void* d_out, int out_size){
    const float* x = (const float*)d_in[0];
    float* out = (float*)d_out;
    precompute_all<<<512 + (BH*(SEQ/2)*DK)/256, 256>>>(x);
    dim3 grid(SEQ/TM, BH);
    qk_attn13<<<grid, 128>>>(out);
}